// round 16
// baseline (speedup 1.0000x reference)
#include <cuda_runtime.h>
#include <cuda_fp16.h>
#include <stdint.h>
#include <math.h>

#define BATCH 4
#define CDIM 128
#define HWDIM 4096
#define NGROUP 8
#define CPG 16
#define NH 4
#define HD 32
#define OC 384   // 3*C

// Scratch (allocation-free: device globals)
__device__ __align__(16) __half g_qh[BATCH * HWDIM * CDIM];      // fp16 [b][t][128], pre-scaled Q
__device__ __align__(16) __half g_kh[BATCH * HWDIM * CDIM];      // fp16 [b][t][128] K
__device__ __align__(16) __half g_vh[BATCH * CDIM * HWDIM];      // fp16 [b][ch][t]  V
__device__ __align__(16) __half g_atth[BATCH * HWDIM * CDIM];    // fp16 [b][t][c] attn out
__device__ float g_ps[BATCH * NGROUP * 8];    // partial sums
__device__ float g_pss[BATCH * NGROUP * 8];   // partial sum-of-squares

__device__ __forceinline__ void mma16(float* d, const uint32_t* a, uint32_t b0, uint32_t b1) {
    asm volatile(
        "mma.sync.aligned.m16n8k16.row.col.f32.f16.f16.f32 "
        "{%0,%1,%2,%3},{%4,%5,%6,%7},{%8,%9},{%0,%1,%2,%3};\n"
        : "+f"(d[0]), "+f"(d[1]), "+f"(d[2]), "+f"(d[3])
        : "r"(a[0]), "r"(a[1]), "r"(a[2]), "r"(a[3]), "r"(b0), "r"(b1));
}

__device__ __forceinline__ void ldm4(uint32_t* r, uint32_t addr) {
    asm volatile("ldmatrix.sync.aligned.m8n8.x4.shared.b16 {%0,%1,%2,%3}, [%4];"
                 : "=r"(r[0]), "=r"(r[1]), "=r"(r[2]), "=r"(r[3]) : "r"(addr));
}

__device__ __forceinline__ void ldm4t(uint32_t* r, uint32_t addr) {
    asm volatile("ldmatrix.sync.aligned.m8n8.x4.trans.shared.b16 {%0,%1,%2,%3}, [%4];"
                 : "=r"(r[0]), "=r"(r[1]), "=r"(r[2]), "=r"(r[3]) : "r"(addr));
}

__device__ __forceinline__ uint32_t packh2(float lo, float hi) {
    __half2 h = __floats2half2_rn(lo, hi);
    return *reinterpret_cast<uint32_t*>(&h);
}

__device__ __forceinline__ uint32_t h2ex2(uint32_t x) {
    uint32_t r;
    asm("ex2.approx.f16x2 %0, %1;" : "=r"(r) : "r"(x));
    return r;
}

__device__ __forceinline__ void cpa16(uint32_t dst, const void* src) {
    asm volatile("cp.async.cg.shared.global [%0], [%1], 16;" :: "r"(dst), "l"(src));
}

__device__ __forceinline__ void sts128u(uint32_t addr, uint32_t a, uint32_t b,
                                        uint32_t c, uint32_t d) {
    asm volatile("st.shared.v4.u32 [%0], {%1,%2,%3,%4};"
                 :: "r"(addr), "r"(a), "r"(b), "r"(c), "r"(d));
}

// ---------------------------------------------------------------------------
// 1. GroupNorm partial sums: 256 CTAs, one 8192-float chunk each.
//    Group (b,g) data is contiguous (16 ch x 4096); chunk idx = bg*8+c.
// ---------------------------------------------------------------------------
__global__ void gn_part_kernel(const float* __restrict__ x) {
    const int idx = blockIdx.x;  // 0..255
    const float4* p = reinterpret_cast<const float4*>(x + (size_t)idx * 8192);
    float s = 0.f, ss = 0.f;
    for (int i = threadIdx.x; i < 2048; i += 256) {
        float4 v = p[i];
        s  += v.x + v.y + v.z + v.w;
        ss += v.x * v.x + v.y * v.y + v.z * v.z + v.w * v.w;
    }
    __shared__ float sh_s[256], sh_ss[256];
    sh_s[threadIdx.x] = s;
    sh_ss[threadIdx.x] = ss;
    __syncthreads();
    for (int off = 128; off > 0; off >>= 1) {
        if (threadIdx.x < off) {
            sh_s[threadIdx.x]  += sh_s[threadIdx.x + off];
            sh_ss[threadIdx.x] += sh_ss[threadIdx.x + off];
        }
        __syncthreads();
    }
    if (threadIdx.x == 0) {
        g_ps[idx]  = sh_s[0];
        g_pss[idx] = sh_ss[0];
    }
}

// Finalize mean/rstd for group bg from its 8 partials.
__device__ __forceinline__ void gn_finalize(int bg, float& mean, float& rstd) {
    float s = 0.f, ss = 0.f;
#pragma unroll
    for (int k = 0; k < 8; k++) {
        s  += g_ps[bg * 8 + k];
        ss += g_pss[bg * 8 + k];
    }
    const float inv = 1.0f / (float)(CPG * HWDIM);
    mean = s * inv;
    float var = ss * inv - mean * mean;
    rstd = rsqrtf(var + 1e-5f);
}

// ---------------------------------------------------------------------------
// 2. QKV GEMM, fp16 tensor cores, GroupNorm fused into the X loader.
//    Out = W @ gn(x) + bias.
//    Q -> g_qh[t][o] pre-scaled; K -> g_kh[t][o-128]; V -> g_vh[o-256][t].
// ---------------------------------------------------------------------------
#define QKV_SMEM (16384 + 32768)

__global__ void __launch_bounds__(256) qkv_h_kernel(const float* __restrict__ W,
                                                    const float* __restrict__ bias,
                                                    const float* __restrict__ x,
                                                    const float* __restrict__ gnw,
                                                    const float* __restrict__ gnb) {
    extern __shared__ char qs[];
    __shared__ float sm_mean[NGROUP], sm_rstd[NGROUP];
    uint32_t ws_u, xs_u;
    asm("{ .reg .u64 t; cvta.to.shared.u64 t, %1; cvt.u32.u64 %0, t; }"
        : "=r"(ws_u) : "l"(qs));
    xs_u = ws_u + 16384;

    const int b = blockIdx.z;
    const int ob0 = blockIdx.y * 64;
    const int t0 = blockIdx.x * 128;
    const int tid = threadIdx.x, warp = tid >> 5, lane = tid & 31;
    const int lr = lane >> 2, lc = lane & 3, r8 = lane & 7, j8 = lane >> 3;

    // ---- GN stats for this batch ----
    if (tid < NGROUP) {
        float mean, rstd;
        gn_finalize(b * NGROUP + tid, mean, rstd);
        sm_mean[tid] = mean;
        sm_rstd[tid] = rstd;
    }
    __syncthreads();

    // ---- W tile: [64 o][128 c] fp32 -> fp16, swizzled ----
    {
        int row = tid >> 2;
#pragma unroll
        for (int i = 0; i < 4; i++) {
            int g = (tid & 3) * 4 + i;
            const float* wp = W + (size_t)(ob0 + row) * CDIM + g * 8;
            float4 wa = *(const float4*)wp;
            float4 wb = *(const float4*)(wp + 4);
            sts128u(ws_u + row * 256 + ((g ^ (row & 7)) << 4),
                    packh2(wa.x, wa.y), packh2(wa.z, wa.w),
                    packh2(wb.x, wb.y), packh2(wb.z, wb.w));
        }
    }
    // ---- X tile: [128 c][128 t], GN applied on the fly, fp32 -> fp16 ----
    {
        int tg = tid & 15, c0 = (tid >> 4) * 8;
        float mean = sm_mean[c0 >> 4], rstd = sm_rstd[c0 >> 4];
#pragma unroll
        for (int j = 0; j < 8; j++) {
            int c = c0 + j;
            float sw = gnw[c] * rstd;
            float sb = gnb[c] - mean * sw;
            const float* p = x + ((size_t)(b * CDIM + c)) * HWDIM + t0 + tg * 8;
            float4 a = *(const float4*)p;
            float4 d = *(const float4*)(p + 4);
            sts128u(xs_u + c * 256 + ((tg ^ (c & 7)) << 4),
                    packh2(a.x * sw + sb, a.y * sw + sb),
                    packh2(a.z * sw + sb, a.w * sw + sb),
                    packh2(d.x * sw + sb, d.y * sw + sb),
                    packh2(d.z * sw + sb, d.w * sw + sb));
        }
    }
    __syncthreads();

    const int wm = warp & 1, wn = warp >> 1;
    float acc[4][2][4];
#pragma unroll
    for (int mi = 0; mi < 4; mi++)
#pragma unroll
        for (int n8 = 0; n8 < 2; n8++)
#pragma unroll
            for (int c = 0; c < 4; c++) acc[mi][n8][c] = 0.f;

#pragma unroll
    for (int ks = 0; ks < 4; ks++) {
        uint32_t bf[2][4];
#pragma unroll
        for (int n8 = 0; n8 < 2; n8++) {
            int row = wn * 16 + n8 * 8 + r8;
            ldm4(bf[n8], ws_u + row * 256 + (((ks * 4 + j8) ^ (row & 7)) << 4));
        }
        uint32_t af[4][2][4];
#pragma unroll
        for (int mi = 0; mi < 4; mi++)
#pragma unroll
            for (int kh = 0; kh < 2; kh++) {
                int c_row = ks * 32 + kh * 16 + (lane & 7) + ((lane >> 4) & 1) * 8;
                int tg = wm * 8 + mi * 2 + ((lane >> 3) & 1);
                ldm4t(af[mi][kh], xs_u + c_row * 256 + ((tg ^ (c_row & 7)) << 4));
            }
#pragma unroll
        for (int mi = 0; mi < 4; mi++)
#pragma unroll
            for (int n8 = 0; n8 < 2; n8++) {
                mma16(acc[mi][n8], af[mi][0], bf[n8][0], bf[n8][1]);
                mma16(acc[mi][n8], af[mi][1], bf[n8][2], bf[n8][3]);
            }
    }

    // ---- epilogue ----
    const float QSC = 0.088388347648318447f * 1.4426950408889634f;  // C^-0.5 * log2(e)
#pragma unroll
    for (int mi = 0; mi < 4; mi++) {
        int t = t0 + wm * 64 + mi * 16 + lr;
#pragma unroll
        for (int n8 = 0; n8 < 2; n8++) {
            int o = ob0 + wn * 16 + n8 * 8 + 2 * lc;
            float b0 = bias[o], b1 = bias[o + 1];
            float v0 = acc[mi][n8][0] + b0, v1 = acc[mi][n8][1] + b1;
            float v2 = acc[mi][n8][2] + b0, v3 = acc[mi][n8][3] + b1;
            if (ob0 < 128) {          // Q: [t][o], pre-scaled
                *(__half2*)(g_qh + ((size_t)b * HWDIM + t) * CDIM + o) =
                    __floats2half2_rn(v0 * QSC, v1 * QSC);
                *(__half2*)(g_qh + ((size_t)b * HWDIM + t + 8) * CDIM + o) =
                    __floats2half2_rn(v2 * QSC, v3 * QSC);
            } else if (ob0 < 256) {   // K: [t][o-128]
                *(__half2*)(g_kh + ((size_t)b * HWDIM + t) * CDIM + (o - 128)) =
                    __floats2half2_rn(v0, v1);
                *(__half2*)(g_kh + ((size_t)b * HWDIM + t + 8) * CDIM + (o - 128)) =
                    __floats2half2_rn(v2, v3);
            } else {                  // V: [ch][t]
                __half* vv = g_vh + (size_t)b * CDIM * HWDIM;
                vv[(size_t)(o - 256) * HWDIM + t]     = __float2half(v0);
                vv[(size_t)(o - 255) * HWDIM + t]     = __float2half(v1);
                vv[(size_t)(o - 256) * HWDIM + t + 8] = __float2half(v2);
                vv[(size_t)(o - 255) * HWDIM + t + 8] = __float2half(v3);
            }
        }
    }
}

// ---------------------------------------------------------------------------
// 3. Flash attention (R14 configuration, best measured 102.1 us):
//    fp16 mma, register-resident P, direct cp.async staging, 64-key tiles
//    in two 32-key halves, double buffer, 16KB smem.
//    256 threads, 8 warps x 32 q = 256 q/CTA.
// ---------------------------------------------------------------------------
#define NT (HWDIM / 64)

__global__ void __launch_bounds__(256, 2) attn_mma_kernel() {
    __shared__ __align__(16) char smem[16384];
    uint32_t smem_u;
    asm("{ .reg .u64 t; cvta.to.shared.u64 t, %1; cvt.u32.u64 %0, t; }"
        : "=r"(smem_u) : "l"(smem));

    const int b = blockIdx.z, h = blockIdx.y;
    const int q0 = blockIdx.x * 256;
    const int tid = threadIdx.x;
    const int warp = tid >> 5, lane = tid & 31;
    const int lr = lane >> 2, lc = lane & 3;
    const int r8 = lane & 7, j8 = lane >> 3;
    const int qbase = warp * 32;

    const __half* Qh = g_qh + (size_t)b * HWDIM * CDIM;
    const __half* Kh = g_kh + (size_t)b * HWDIM * CDIM;
    const __half* Vh = g_vh + ((size_t)b * CDIM + h * HD) * HWDIM;

    // tile-load indices: 1 K chunk + 1 V chunk per thread
    const int lk_key = tid >> 2, lk_g = tid & 3;   // K: row=key(64), 4x16B chunks
    const int lv_ch  = tid >> 3, lv_g = tid & 7;   // V: row=ch(32), 8x16B chunks

    // ---- stage tile 0 into buf 0 ----
    cpa16(smem_u + lk_key * 64 + ((lk_g ^ ((lk_key >> 1) & 3)) << 4),
          Kh + (size_t)lk_key * CDIM + h * HD + lk_g * 8);
    cpa16(smem_u + 8192 + lv_ch * 128 + ((lv_g ^ (lv_ch & 7)) << 4),
          Vh + (size_t)lv_ch * HWDIM + lv_g * 8);
    asm volatile("cp.async.commit_group;" ::: "memory");

    // ---- Q fragments (fp16 pre-scaled) ----
    uint32_t qa[2][2][4];
#pragma unroll
    for (int mf = 0; mf < 2; mf++) {
        int qrow = q0 + qbase + mf * 16 + lr;
#pragma unroll
        for (int ks = 0; ks < 2; ks++) {
            int cc = h * HD + 2 * lc + 16 * ks;
            qa[mf][ks][0] = *(const uint32_t*)(Qh + (size_t)qrow * CDIM + cc);
            qa[mf][ks][1] = *(const uint32_t*)(Qh + (size_t)(qrow + 8) * CDIM + cc);
            qa[mf][ks][2] = *(const uint32_t*)(Qh + (size_t)qrow * CDIM + cc + 8);
            qa[mf][ks][3] = *(const uint32_t*)(Qh + (size_t)(qrow + 8) * CDIM + cc + 8);
        }
    }

    float l_i[2][2] = {{0.f, 0.f}, {0.f, 0.f}};
    float oacc[2][4][4];
#pragma unroll
    for (int mf = 0; mf < 2; mf++)
#pragma unroll
        for (int nf = 0; nf < 4; nf++)
#pragma unroll
            for (int c = 0; c < 4; c++) oacc[mf][nf][c] = 0.f;

    for (int t = 0; t < NT; t++) {
        // ---- stage tile t+1 into the other buffer ----
        if (t < NT - 1) {
            const int j0n = (t + 1) * 64;
            const int nb = (t + 1) & 1;
            cpa16(smem_u + nb * 4096 + lk_key * 64 + ((lk_g ^ ((lk_key >> 1) & 3)) << 4),
                  Kh + (size_t)(j0n + lk_key) * CDIM + h * HD + lk_g * 8);
            cpa16(smem_u + 8192 + nb * 4096 + lv_ch * 128 + ((lv_g ^ (lv_ch & 7)) << 4),
                  Vh + (size_t)lv_ch * HWDIM + j0n + lv_g * 8);
            asm volatile("cp.async.commit_group;" ::: "memory");
            asm volatile("cp.async.wait_group 1;" ::: "memory");
        } else {
            asm volatile("cp.async.wait_group 0;" ::: "memory");
        }
        __syncthreads();  // tile t visible to all threads

        const uint32_t kfb = smem_u + (t & 1) * 4096;
        const uint32_t vfb = smem_u + 8192 + (t & 1) * 4096;

        // ==== process tile in two 32-key halves (bounded liveness) ====
#pragma unroll
        for (int hh2 = 0; hh2 < 2; hh2++) {
            // ---- S = Q @ K^T for keys [32*hh2, 32*hh2+32) ----
            float sacc[2][4][4];
#pragma unroll
            for (int mf = 0; mf < 2; mf++)
#pragma unroll
                for (int nfl = 0; nfl < 4; nfl++)
#pragma unroll
                    for (int c = 0; c < 4; c++) sacc[mf][nfl][c] = 0.f;

#pragma unroll
            for (int nfl = 0; nfl < 4; nfl++) {
                uint32_t kb[4];
                int row = hh2 * 32 + nfl * 8 + r8;
                ldm4(kb, kfb + row * 64 + ((j8 ^ ((row >> 1) & 3)) << 4));
#pragma unroll
                for (int mf = 0; mf < 2; mf++) {
                    mma16(sacc[mf][nfl], qa[mf][0], kb[0], kb[1]);
                    mma16(sacc[mf][nfl], qa[mf][1], kb[2], kb[3]);
                }
            }

            // ---- exp2 -> fp16 P (registers), row sums ----
            uint32_t ph[2][2][4];
#pragma unroll
            for (int mf = 0; mf < 2; mf++) {
#pragma unroll
                for (int nfl = 0; nfl < 4; nfl++) {
                    ph[mf][0][nfl] = h2ex2(packh2(sacc[mf][nfl][0], sacc[mf][nfl][1]));
                    ph[mf][1][nfl] = h2ex2(packh2(sacc[mf][nfl][2], sacc[mf][nfl][3]));
                }
#pragma unroll
                for (int ri = 0; ri < 2; ri++) {
                    const uint32_t* p = ph[mf][ri];
                    __half2 s0 = __hadd2(*(__half2*)&p[0], *(__half2*)&p[1]);
                    __half2 s1 = __hadd2(*(__half2*)&p[2], *(__half2*)&p[3]);
                    __half2 s = __hadd2(s0, s1);
                    float2 f = __half22float2(s);
                    float sum = f.x + f.y;
                    sum += __shfl_xor_sync(0xffffffffu, sum, 1);
                    sum += __shfl_xor_sync(0xffffffffu, sum, 2);
                    l_i[mf][ri] += sum;
                }
            }

            // ---- V b-frags for this key half ----
            uint32_t vbl[4][4];
#pragma unroll
            for (int nf = 0; nf < 4; nf++) {
                int row = nf * 8 + r8;
                int g = hh2 * 4 + j8;
                ldm4(vbl[nf], vfb + row * 128 + ((g ^ r8) << 4));
            }

            // ---- O += P @ V (A-frags direct from ph registers) ----
#pragma unroll
            for (int mf = 0; mf < 2; mf++) {
#pragma unroll
                for (int kql = 0; kql < 2; kql++) {
                    uint32_t pa[4] = {ph[mf][0][2 * kql], ph[mf][1][2 * kql],
                                      ph[mf][0][2 * kql + 1], ph[mf][1][2 * kql + 1]};
#pragma unroll
                    for (int nf = 0; nf < 4; nf++)
                        mma16(oacc[mf][nf], pa, vbl[nf][2 * kql], vbl[nf][2 * kql + 1]);
                }
            }
        }
        __syncthreads();  // all reads of buf t&1 done before it is re-staged
    }

    // ---- epilogue: fp16 [t][c] output ----
#pragma unroll
    for (int mf = 0; mf < 2; mf++)
#pragma unroll
        for (int ri = 0; ri < 2; ri++) {
            float inv = 1.f / l_i[mf][ri];
            int q = q0 + qbase + mf * 16 + lr + 8 * ri;
#pragma unroll
            for (int nf = 0; nf < 4; nf++) {
                int ch = h * HD + nf * 8 + 2 * lc;
                *(uint32_t*)(g_atth + ((size_t)b * HWDIM + q) * CDIM + ch) =
                    packh2(oacc[mf][nf][2 * ri] * inv, oacc[mf][nf][2 * ri + 1] * inv);
            }
        }
}

// ---------------------------------------------------------------------------
// 4. Projection GEMM, fp16 tensor cores; epilogue adds bias + recomputed
//    GroupNorm residual (stats finalized in-kernel from partials).
// ---------------------------------------------------------------------------
#define PROJ_SMEM (16384 + 32768)

__global__ void __launch_bounds__(256) proj_h_kernel(const float* __restrict__ W,
                                                     const float* __restrict__ bias,
                                                     float* __restrict__ Out,
                                                     const float* __restrict__ x,
                                                     const float* __restrict__ gnw,
                                                     const float* __restrict__ gnb) {
    extern __shared__ char qs[];
    __shared__ float sm_mean[NGROUP], sm_rstd[NGROUP];
    uint32_t ws_u, as_u;
    asm("{ .reg .u64 t; cvta.to.shared.u64 t, %1; cvt.u32.u64 %0, t; }"
        : "=r"(ws_u) : "l"(qs));
    as_u = ws_u + 16384;

    const int b = blockIdx.z;
    const int ob0 = blockIdx.y * 64;
    const int t0 = blockIdx.x * 128;
    const int tid = threadIdx.x, warp = tid >> 5, lane = tid & 31;
    const int lr = lane >> 2, lc = lane & 3, r8 = lane & 7, j8 = lane >> 3;

    if (tid < NGROUP) {
        float mean, rstd;
        gn_finalize(b * NGROUP + tid, mean, rstd);
        sm_mean[tid] = mean;
        sm_rstd[tid] = rstd;
    }

    // ---- W tile ----
    {
        int row = tid >> 2;
#pragma unroll
        for (int i = 0; i < 4; i++) {
            int g = (tid & 3) * 4 + i;
            const float* wp = W + (size_t)(ob0 + row) * CDIM + g * 8;
            float4 wa = *(const float4*)wp;
            float4 wb = *(const float4*)(wp + 4);
            sts128u(ws_u + row * 256 + ((g ^ (row & 7)) << 4),
                    packh2(wa.x, wa.y), packh2(wa.z, wa.w),
                    packh2(wb.x, wb.y), packh2(wb.z, wb.w));
        }
    }
    // ---- A tile: [128 t][128 c] fp16 via cp.async ----
    {
        int tg = tid & 15, row0 = tid >> 4;
        const __half* ap = g_atth + (size_t)b * HWDIM * CDIM;
#pragma unroll
        for (int j = 0; j < 8; j++) {
            int row = row0 + 16 * j;
            cpa16(as_u + row * 256 + ((tg ^ (row & 7)) << 4),
                  ap + (size_t)(t0 + row) * CDIM + tg * 8);
        }
        asm volatile("cp.async.commit_group;" ::: "memory");
    }
    asm volatile("cp.async.wait_group 0;" ::: "memory");
    __syncthreads();

    const int wm = warp & 1, wn = warp >> 1;
    float acc[4][2][4];
#pragma unroll
    for (int mi = 0; mi < 4; mi++)
#pragma unroll
        for (int n8 = 0; n8 < 2; n8++)
#pragma unroll
            for (int c = 0; c < 4; c++) acc[mi][n8][c] = 0.f;

#pragma unroll
    for (int ks = 0; ks < 4; ks++) {
        uint32_t bf[2][4];
#pragma unroll
        for (int n8 = 0; n8 < 2; n8++) {
            int row = wn * 16 + n8 * 8 + r8;
            ldm4(bf[n8], ws_u + row * 256 + (((ks * 4 + j8) ^ (row & 7)) << 4));
        }
        uint32_t af[4][2][4];
#pragma unroll
        for (int mi = 0; mi < 4; mi++)
#pragma unroll
            for (int kh = 0; kh < 2; kh++) {
                int row = wm * 64 + mi * 16 + ((j8 & 1) << 3) + r8;
                int g = ks * 4 + kh * 2 + (j8 >> 1);
                ldm4(af[mi][kh], as_u + row * 256 + ((g ^ (row & 7)) << 4));
            }
#pragma unroll
        for (int mi = 0; mi < 4; mi++)
#pragma unroll
            for (int n8 = 0; n8 < 2; n8++) {
                mma16(acc[mi][n8], af[mi][0], bf[n8][0], bf[n8][1]);
                mma16(acc[mi][n8], af[mi][1], bf[n8][2], bf[n8][3]);
            }
    }

    // ---- epilogue: fp32 + bias + recomputed GN residual ----
#pragma unroll
    for (int mi = 0; mi < 4; mi++) {
        int t = t0 + wm * 64 + mi * 16 + lr;
#pragma unroll
        for (int n8 = 0; n8 < 2; n8++) {
            int o = ob0 + wn * 16 + n8 * 8 + 2 * lc;
            float mean = sm_mean[o >> 4], rstd = sm_rstd[o >> 4];
            float sw0 = gnw[o] * rstd,     sb0 = gnb[o] - mean * sw0;
            float sw1 = gnw[o + 1] * rstd, sb1 = gnb[o + 1] - mean * sw1;
            float b0 = bias[o], b1 = bias[o + 1];
            size_t i00 = ((size_t)b * CDIM + o) * HWDIM + t;
            size_t i10 = i00 + HWDIM;
            Out[i00]     = acc[mi][n8][0] + b0 + x[i00] * sw0 + sb0;
            Out[i10]     = acc[mi][n8][1] + b1 + x[i10] * sw1 + sb1;
            Out[i00 + 8] = acc[mi][n8][2] + b0 + x[i00 + 8] * sw0 + sb0;
            Out[i10 + 8] = acc[mi][n8][3] + b1 + x[i10 + 8] * sw1 + sb1;
        }
    }
}

// ---------------------------------------------------------------------------
// Launch
// ---------------------------------------------------------------------------
extern "C" void kernel_launch(void* const* d_in, const int* in_sizes, int n_in,
                              void* d_out, int out_size) {
    const float* x      = (const float*)d_in[0];
    const float* gn_w   = (const float*)d_in[1];
    const float* gn_b   = (const float*)d_in[2];
    const float* qkv_w  = (const float*)d_in[3];
    const float* qkv_b  = (const float*)d_in[4];
    const float* proj_w = (const float*)d_in[5];
    const float* proj_b = (const float*)d_in[6];
    float* out = (float*)d_out;

    static bool attr_set = false;
    if (!attr_set) {
        cudaFuncSetAttribute(qkv_h_kernel,
                             cudaFuncAttributeMaxDynamicSharedMemorySize, QKV_SMEM);
        cudaFuncSetAttribute(proj_h_kernel,
                             cudaFuncAttributeMaxDynamicSharedMemorySize, PROJ_SMEM);
        attr_set = true;
    }

    gn_part_kernel<<<BATCH * NGROUP * 8, 256>>>(x);
    qkv_h_kernel<<<dim3(HWDIM / 128, OC / 64, BATCH), 256, QKV_SMEM>>>(
        qkv_w, qkv_b, x, gn_w, gn_b);
    attn_mma_kernel<<<dim3(HWDIM / 256, NH, BATCH), 256>>>();
    proj_h_kernel<<<dim3(HWDIM / 128, CDIM / 64, BATCH), 256, PROJ_SMEM>>>(
        proj_w, proj_b, out, x, gn_w, gn_b);
}